// round 1
// baseline (speedup 1.0000x reference)
#include <cuda_runtime.h>

#define BATCH   256
#define NWARM   128
#define FEAT    1024
#define HID     2048
#define TSTEPS  128
#define OUT_T   (TSTEPS + 1)
#define LDOUT   (OUT_T * FEAT)

// Scratch: ping-pong hidden state + combined cell bias (allocation-free rule:
// __device__ globals).
__device__ float g_h[2][BATCH * HID];
__device__ float g_bias_cell[HID];

__global__ void init_kernel(const float* __restrict__ b_ih,
                            const float* __restrict__ b_hh) {
    int i = blockIdx.x * blockDim.x + threadIdx.x;
    if (i < HID) g_bias_cell[i] = b_ih[i] + b_hh[i];
    if (i < BATCH * HID) g_h[0][i] = 0.0f;
}

// C[m,n] = act( sum_k A1[m,k]*W1[n,k] + sum_k A2[m,k]*W2[n,k] + bias[n] )
// A row-major with stride lda; W row-major (N x K), K contiguous (TN GEMM).
// BN=64 fixed, BK=16 fixed, 256 threads. BM/TM templated (64/4 cell, 32/2 fc).
template<int BM, int TM, bool RELU>
__global__ __launch_bounds__(256)
void rnn_gemm(const float* __restrict__ A1, int lda1,
              const float* __restrict__ W1, int K1,
              const float* __restrict__ A2, int lda2,
              const float* __restrict__ W2, int K2,
              const float* __restrict__ bias,
              float* __restrict__ C, int ldc)
{
    constexpr int BN = 64, BK = 16, TN = 4;
    // Pads chosen so transposed stores are (near) conflict-free:
    //  As row BM+2 -> store banks kc*2 + r, all distinct.
    //  Bs row BN+4 -> 2-way store conflict, rows stay 16B-aligned for LDS.128.
    __shared__ float As[BK][BM + 2];
    __shared__ float Bs[BK][BN + 4];

    const int tid = threadIdx.x;
    const int tx  = tid & 15;           // BN/TN = 16 columns of threads
    const int ty  = tid >> 4;           // BM/TM = 16 rows of threads
    const int bm  = blockIdx.y * BM;
    const int bn  = blockIdx.x * BN;

    const int t1   = K1 >> 4;
    const int tTot = t1 + (K2 >> 4);

    // per-thread load slots (one float4 each)
    const int  ar      = tid >> 2;
    const int  akc     = (tid & 3) * 4;
    const bool aActive = tid < BM * 4;

    float4 aReg, bReg;

    auto ldTile = [&](int tt) {
        const float* A; const float* W; int lda, K, kt;
        if (tt < t1) { A = A1; W = W1; lda = lda1; K = K1; kt = tt << 4; }
        else         { A = A2; W = W2; lda = lda2; K = K2; kt = (tt - t1) << 4; }
        if (aActive)
            aReg = *(const float4*)(A + (size_t)(bm + ar) * lda + kt + akc);
        bReg = *(const float4*)(W + (size_t)(bn + ar) * K + kt + akc);
    };
    auto stTile = [&]() {
        if (aActive) {
            As[akc + 0][ar] = aReg.x; As[akc + 1][ar] = aReg.y;
            As[akc + 2][ar] = aReg.z; As[akc + 3][ar] = aReg.w;
        }
        Bs[akc + 0][ar] = bReg.x; Bs[akc + 1][ar] = bReg.y;
        Bs[akc + 2][ar] = bReg.z; Bs[akc + 3][ar] = bReg.w;
    };

    float acc[TM][TN];
    #pragma unroll
    for (int i = 0; i < TM; i++)
        #pragma unroll
        for (int j = 0; j < TN; j++) acc[i][j] = 0.0f;

    ldTile(0);
    stTile();
    __syncthreads();

    for (int tt = 0; tt < tTot; tt++) {
        if (tt + 1 < tTot) ldTile(tt + 1);   // reg prefetch hides L2 latency
        #pragma unroll
        for (int k = 0; k < BK; k++) {
            float a[TM];
            #pragma unroll
            for (int i = 0; i < TM; i++) a[i] = As[k][ty * TM + i];
            float4 b4 = *(const float4*)&Bs[k][tx * TN];
            float bv[TN] = {b4.x, b4.y, b4.z, b4.w};
            #pragma unroll
            for (int i = 0; i < TM; i++)
                #pragma unroll
                for (int j = 0; j < TN; j++)
                    acc[i][j] += a[i] * bv[j];
        }
        __syncthreads();
        if (tt + 1 < tTot) {
            stTile();
            __syncthreads();
        }
    }

    const float4 bb = *(const float4*)&bias[bn + tx * TN];
    #pragma unroll
    for (int i = 0; i < TM; i++) {
        int m = bm + ty * TM + i;
        float4 o;
        o.x = acc[i][0] + bb.x;
        o.y = acc[i][1] + bb.y;
        o.z = acc[i][2] + bb.z;
        o.w = acc[i][3] + bb.w;
        if (RELU) {
            o.x = fmaxf(o.x, 0.0f); o.y = fmaxf(o.y, 0.0f);
            o.z = fmaxf(o.z, 0.0f); o.w = fmaxf(o.w, 0.0f);
        }
        *(float4*)(C + (size_t)m * ldc + bn + tx * TN) = o;
    }
}

extern "C" void kernel_launch(void* const* d_in, const int* in_sizes, int n_in,
                              void* d_out, int out_size)
{
    const float* inputs = (const float*)d_in[0];   // [256,128,1024]
    const float* W_ih   = (const float*)d_in[1];   // [2048,1024]
    const float* b_ih   = (const float*)d_in[2];   // [2048]
    const float* W_hh   = (const float*)d_in[3];   // [2048,2048]
    const float* b_hh   = (const float*)d_in[4];   // [2048]
    const float* W_fc   = (const float*)d_in[5];   // [1024,2048]
    const float* b_fc   = (const float*)d_in[6];   // [1024]
    float* out = (float*)d_out;                    // [256,129,1024]

    float* h_base = nullptr; float* bias_cell = nullptr;
    cudaGetSymbolAddress((void**)&h_base, g_h);
    cudaGetSymbolAddress((void**)&bias_cell, g_bias_cell);
    float* h[2] = { h_base, h_base + (size_t)BATCH * HID };

    init_kernel<<<(BATCH * HID + 255) / 256, 256>>>(b_ih, b_hh);

    dim3 cellGrid(HID / 64, BATCH / 64);   // 32 x 4 = 128 CTAs
    dim3 fcGrid(FEAT / 64, BATCH / 32);    // 16 x 8 = 128 CTAs

    int cur = 0;
    // warmup scan over inputs time axis
    for (int t = 0; t < NWARM; t++) {
        rnn_gemm<64, 4, true><<<cellGrid, 256>>>(
            inputs + (size_t)t * FEAT, NWARM * FEAT, W_ih, FEAT,
            h[cur], HID, W_hh, HID,
            bias_cell, h[cur ^ 1], HID);
        cur ^= 1;
    }
    // pred0 -> out[:, 0, :]
    rnn_gemm<32, 2, false><<<fcGrid, 256>>>(
        h[cur], HID, W_fc, HID,
        nullptr, 0, nullptr, 0,
        b_fc, out, LDOUT);
    // autoregressive rollout: x_t = out[:, s-1, :]
    for (int s = 1; s <= TSTEPS; s++) {
        rnn_gemm<64, 4, true><<<cellGrid, 256>>>(
            out + (size_t)(s - 1) * FEAT, LDOUT, W_ih, FEAT,
            h[cur], HID, W_hh, HID,
            bias_cell, h[cur ^ 1], HID);
        cur ^= 1;
        rnn_gemm<32, 2, false><<<fcGrid, 256>>>(
            h[cur], HID, W_fc, HID,
            nullptr, 0, nullptr, 0,
            b_fc, out + (size_t)s * FEAT, LDOUT);
    }
}

// round 4
// speedup vs baseline: 2.0036x; 2.0036x over previous
#include <cuda_runtime.h>
#include <cuda_bf16.h>
#include <stdint.h>

#define BATCH   256
#define NWARM   128
#define FEAT    1024
#define HID     2048
#define TSTEPS  128
#define OUT_T   (TSTEPS + 1)
#define LDOUT   (OUT_T * FEAT)

// Scratch: ping-pong hidden state + combined cell bias only (same footprint
// as the round-1 kernel that passed; allocation-free rule -> __device__).
__device__ float g_h[2][BATCH * HID];
__device__ float g_bias_cell[HID];

__global__ void init_kernel(const float* __restrict__ b_ih,
                            const float* __restrict__ b_hh)
{
    int i = blockIdx.x * blockDim.x + threadIdx.x;
    if (i < HID) g_bias_cell[i] = b_ih[i] + b_hh[i];
    if (i < BATCH * HID) g_h[0][i] = 0.0f;
}

__device__ __forceinline__ unsigned pkb(__nv_bfloat16 a, __nv_bfloat16 b) {
    return ((unsigned)__bfloat16_as_ushort(b) << 16) | (unsigned)__bfloat16_as_ushort(a);
}

// split fp32x4 -> bf16 hi pair + bf16 lo pair
__device__ __forceinline__ void split4(float4 v, uint2& H, uint2& L) {
    __nv_bfloat16 hx = __float2bfloat16(v.x), hy = __float2bfloat16(v.y);
    __nv_bfloat16 hz = __float2bfloat16(v.z), hw = __float2bfloat16(v.w);
    H.x = pkb(hx, hy); H.y = pkb(hz, hw);
    L.x = pkb(__float2bfloat16(v.x - __bfloat162float(hx)),
              __float2bfloat16(v.y - __bfloat162float(hy)));
    L.y = pkb(__float2bfloat16(v.z - __bfloat162float(hz)),
              __float2bfloat16(v.w - __bfloat162float(hw)));
}

__device__ __forceinline__ void mma16816(float d[4], const unsigned a[4], const unsigned b[2]) {
    asm volatile(
        "mma.sync.aligned.m16n8k16.row.col.f32.bf16.bf16.f32 "
        "{%0,%1,%2,%3}, {%4,%5,%6,%7}, {%8,%9}, {%0,%1,%2,%3};"
        : "+f"(d[0]), "+f"(d[1]), "+f"(d[2]), "+f"(d[3])
        : "r"(a[0]), "r"(a[1]), "r"(a[2]), "r"(a[3]), "r"(b[0]), "r"(b[1]));
}

// C[m,n] = act( sum_k A[m,k]*W[n,k] + bias[n] ), K split across 2 segments.
// A and W are fp32 in gmem; both are split to bf16 (hi,lo) on the fly.
// D = Ah*Wh + Ah*Wl + Al*Wh  (fp32 accumulate in tensor cores).
// BM=64, BK=32 fixed; 128 threads, warp-grid 2x2, warp tile 32 x (BN/2).
template<int BN, bool RELU>
__global__ __launch_bounds__(128)
void gemm_split(const float* __restrict__ A1, int lda1,
                const float* __restrict__ W1, int K1,
                const float* __restrict__ A2, int lda2,
                const float* __restrict__ W2, int K2,
                const float* __restrict__ bias,
                float* __restrict__ C, int ldc)
{
    constexpr int BM = 64, PK = 40;      // PK: 80B pitch -> conflict-free frags
    constexpr int WNJ = BN / 16;         // n8-frags per warp (warp n-span = BN/2)
    constexpr int WIW = BN / 16;         // W-load float4s per thread

    __shared__ __nv_bfloat16 sA[2][2][BM * PK];   // [buf][hi/lo]
    __shared__ __nv_bfloat16 sB[2][2][BN * PK];

    const int tid  = threadIdx.x;
    const int lane = tid & 31;
    const int wid  = tid >> 5;
    const int wm   = wid & 1;
    const int wn   = wid >> 1;
    const int lr   = lane >> 2;
    const int lc   = lane & 3;
    const int bm   = blockIdx.y * BM;
    const int bn   = blockIdx.x * BN;

    const int t1   = K1 >> 5;
    const int tTot = t1 + (K2 >> 5);

    const int ldr = tid >> 3;          // 0..15 row-group base
    const int ldc4 = (tid & 7) * 4;    // fp32 chunk offset in BK=32

    float4 av[4];
    float4 wv[WIW];

#define LDTILE(TT)                                                          \
    do {                                                                    \
        const float *A_, *W_; int lda_, K_, kt_;                            \
        if ((TT) < t1) { A_ = A1; W_ = W1; lda_ = lda1; K_ = K1; kt_ = (TT) << 5; } \
        else           { A_ = A2; W_ = W2; lda_ = lda2; K_ = K2; kt_ = ((TT) - t1) << 5; } \
        _Pragma("unroll")                                                   \
        for (int p = 0; p < 4; p++) {                                       \
            int r = ldr + p * 16;                                           \
            av[p] = *(const float4*)(A_ + (size_t)(bm + r) * lda_ + kt_ + ldc4); \
        }                                                                   \
        _Pragma("unroll")                                                   \
        for (int p = 0; p < WIW; p++) {                                     \
            int r = ldr + p * 16;                                           \
            wv[p] = *(const float4*)(W_ + (size_t)(bn + r) * K_ + kt_ + ldc4); \
        }                                                                   \
    } while (0)

#define STTILE(BUF)                                                         \
    do {                                                                    \
        _Pragma("unroll")                                                   \
        for (int p = 0; p < 4; p++) {                                       \
            int r = ldr + p * 16;                                           \
            uint2 H, L; split4(av[p], H, L);                                \
            *(uint2*)&sA[(BUF)][0][r * PK + ldc4] = H;                      \
            *(uint2*)&sA[(BUF)][1][r * PK + ldc4] = L;                      \
        }                                                                   \
        _Pragma("unroll")                                                   \
        for (int p = 0; p < WIW; p++) {                                     \
            int r = ldr + p * 16;                                           \
            uint2 H, L; split4(wv[p], H, L);                                \
            *(uint2*)&sB[(BUF)][0][r * PK + ldc4] = H;                      \
            *(uint2*)&sB[(BUF)][1][r * PK + ldc4] = L;                      \
        }                                                                   \
    } while (0)

    float D[2][WNJ][4];
    #pragma unroll
    for (int i = 0; i < 2; i++)
        #pragma unroll
        for (int j = 0; j < WNJ; j++)
            #pragma unroll
            for (int q = 0; q < 4; q++) D[i][j][q] = 0.0f;

    LDTILE(0);
    STTILE(0);
    __syncthreads();

    for (int tt = 0; tt < tTot; tt++) {
        const int buf = tt & 1;
        if (tt + 1 < tTot) LDTILE(tt + 1);

        #pragma unroll
        for (int k16 = 0; k16 < 2; k16++) {
            const int k0 = k16 * 16;
            unsigned Ah[2][4], Al[2][4];
            #pragma unroll
            for (int mi = 0; mi < 2; mi++) {
                int m0 = wm * 32 + mi * 16;
                const __nv_bfloat16* ph = &sA[buf][0][(m0 + lr) * PK + k0 + 2 * lc];
                const __nv_bfloat16* pl = &sA[buf][1][(m0 + lr) * PK + k0 + 2 * lc];
                Ah[mi][0] = *(const unsigned*)ph;
                Ah[mi][1] = *(const unsigned*)(ph + 8 * PK);
                Ah[mi][2] = *(const unsigned*)(ph + 8);
                Ah[mi][3] = *(const unsigned*)(ph + 8 * PK + 8);
                Al[mi][0] = *(const unsigned*)pl;
                Al[mi][1] = *(const unsigned*)(pl + 8 * PK);
                Al[mi][2] = *(const unsigned*)(pl + 8);
                Al[mi][3] = *(const unsigned*)(pl + 8 * PK + 8);
            }
            unsigned Bh[WNJ][2], Bl[WNJ][2];
            #pragma unroll
            for (int nj = 0; nj < WNJ; nj++) {
                int n0 = wn * (BN / 2) + nj * 8;
                const __nv_bfloat16* ph = &sB[buf][0][(n0 + lr) * PK + k0 + 2 * lc];
                const __nv_bfloat16* pl = &sB[buf][1][(n0 + lr) * PK + k0 + 2 * lc];
                Bh[nj][0] = *(const unsigned*)ph;
                Bh[nj][1] = *(const unsigned*)(ph + 8);
                Bl[nj][0] = *(const unsigned*)pl;
                Bl[nj][1] = *(const unsigned*)(pl + 8);
            }
            #pragma unroll
            for (int mi = 0; mi < 2; mi++)
                #pragma unroll
                for (int nj = 0; nj < WNJ; nj++) {
                    mma16816(D[mi][nj], Ah[mi], Bh[nj]);
                    mma16816(D[mi][nj], Ah[mi], Bl[nj]);
                    mma16816(D[mi][nj], Al[mi], Bh[nj]);
                }
        }

        if (tt + 1 < tTot) STTILE(buf ^ 1);
        __syncthreads();
    }

#undef LDTILE
#undef STTILE

    // epilogue
    #pragma unroll
    for (int mi = 0; mi < 2; mi++) {
        #pragma unroll
        for (int nj = 0; nj < WNJ; nj++) {
            int r = bm + wm * 32 + mi * 16 + lr;
            int c = bn + wn * (BN / 2) + nj * 8 + lc * 2;
            float2 bb = *(const float2*)&bias[c];
            float v0 = D[mi][nj][0] + bb.x;
            float v1 = D[mi][nj][1] + bb.y;
            float v2 = D[mi][nj][2] + bb.x;
            float v3 = D[mi][nj][3] + bb.y;
            if (RELU) {
                v0 = fmaxf(v0, 0.0f); v1 = fmaxf(v1, 0.0f);
                v2 = fmaxf(v2, 0.0f); v3 = fmaxf(v3, 0.0f);
            }
            *(float2*)(C + (size_t)r * ldc + c)       = make_float2(v0, v1);
            *(float2*)(C + (size_t)(r + 8) * ldc + c) = make_float2(v2, v3);
        }
    }
}

extern "C" void kernel_launch(void* const* d_in, const int* in_sizes, int n_in,
                              void* d_out, int out_size)
{
    const float* inputs = (const float*)d_in[0];   // [256,128,1024]
    const float* W_ih   = (const float*)d_in[1];   // [2048,1024]
    const float* b_ih   = (const float*)d_in[2];
    const float* W_hh   = (const float*)d_in[3];   // [2048,2048]
    const float* b_hh   = (const float*)d_in[4];
    const float* W_fc   = (const float*)d_in[5];   // [1024,2048]
    const float* b_fc   = (const float*)d_in[6];
    float* out = (float*)d_out;                    // [256,129,1024]

    float* h_base = nullptr; float* bias_cell = nullptr;
    cudaGetSymbolAddress((void**)&h_base, g_h);
    cudaGetSymbolAddress((void**)&bias_cell, g_bias_cell);
    float* h[2] = { h_base, h_base + (size_t)BATCH * HID };

    init_kernel<<<(BATCH * HID + 255) / 256, 256>>>(b_ih, b_hh);

    dim3 cellGrid(HID / 64, BATCH / 64);   // 32 x 4 = 128 CTAs
    dim3 fcGrid(FEAT / 32, BATCH / 64);    // 32 x 4 = 128 CTAs

    int cur = 0;
    for (int t = 0; t < NWARM; t++) {
        gemm_split<64, true><<<cellGrid, 128>>>(
            inputs + (size_t)t * FEAT, NWARM * FEAT, W_ih, FEAT,
            h[cur], HID, W_hh, HID,
            bias_cell, h[cur ^ 1], HID);
        cur ^= 1;
    }
    gemm_split<32, false><<<fcGrid, 128>>>(
        h[cur], HID, W_fc, HID,
        nullptr, 0, nullptr, 0,
        b_fc, out, LDOUT);
    for (int s = 1; s <= TSTEPS; s++) {
        gemm_split<64, true><<<cellGrid, 128>>>(
            out + (size_t)(s - 1) * FEAT, LDOUT, W_ih, FEAT,
            h[cur], HID, W_hh, HID,
            bias_cell, h[cur ^ 1], HID);
        cur ^= 1;
        gemm_split<32, false><<<fcGrid, 128>>>(
            h[cur], HID, W_fc, HID,
            nullptr, 0, nullptr, 0,
            b_fc, out + (size_t)s * FEAT, LDOUT);
    }
}